// round 1
// baseline (speedup 1.0000x reference)
#include <cuda_runtime.h>
#include <math.h>

#define BB   8
#define CC   64
#define CR   8
#define HH   64
#define WWD  64
#define NPIX 4096   // HH*WWD

// ---------------- device scratch (static, no allocation) ----------------
__device__ float d_avg[BB * CC];
__device__ float d_maxv[BB * CC];
__device__ float d_ca[BB * CC];
__device__ float d_sa_avg[BB * NPIX];
__device__ float d_sa_max[BB * NPIX];
__device__ float d_sa_mask[BB * NPIX];
// PAM fallback scratch (only written when gamma != 0)
__device__ float d_q[BB * CR * NPIX];
__device__ float d_k[BB * CR * NPIX];
__device__ float d_v[BB * CC * NPIX];
__device__ float d_pam[BB * CC * NPIX];

// ---------------- K1: per-(b,c) mean & max over HW ----------------
__global__ void k_chanstats(const float* __restrict__ x) {
    const int bc = blockIdx.x;                 // 0 .. B*C-1
    const float4* xp = reinterpret_cast<const float4*>(x + (size_t)bc * NPIX);
    float s = 0.0f, m = -INFINITY;
    for (int i = threadIdx.x; i < NPIX / 4; i += blockDim.x) {
        float4 v = xp[i];
        s += v.x + v.y + v.z + v.w;
        m = fmaxf(m, fmaxf(fmaxf(v.x, v.y), fmaxf(v.z, v.w)));
    }
    // warp reduce
    for (int off = 16; off > 0; off >>= 1) {
        s += __shfl_down_sync(0xffffffffu, s, off);
        m  = fmaxf(m, __shfl_down_sync(0xffffffffu, m, off));
    }
    __shared__ float ss[8], sm[8];
    const int wid = threadIdx.x >> 5, lid = threadIdx.x & 31;
    if (lid == 0) { ss[wid] = s; sm[wid] = m; }
    __syncthreads();
    if (threadIdx.x == 0) {
        float ts = 0.0f, tm = -INFINITY;
        const int nw = blockDim.x >> 5;
        for (int i = 0; i < nw; i++) { ts += ss[i]; tm = fmaxf(tm, sm[i]); }
        d_avg[bc]  = ts * (1.0f / NPIX);
        d_maxv[bc] = tm;
    }
}

// ---------------- K2: channel-attention MLP (one block per batch) ----------------
__global__ void k_mlp(const float* __restrict__ fc1,   // [CR, C]
                      const float* __restrict__ fc2) { // [C, CR]
    const int b = blockIdx.x;
    const int t = threadIdx.x;  // 64 threads
    __shared__ float s_avg[CC], s_mx[CC], h_avg[CR], h_mx[CR];
    s_avg[t] = d_avg[b * CC + t];
    s_mx[t]  = d_maxv[b * CC + t];
    __syncthreads();
    if (t < CR) {
        float ha = 0.0f, hm = 0.0f;
        #pragma unroll
        for (int c = 0; c < CC; c++) {
            const float w = fc1[t * CC + c];
            ha += s_avg[c] * w;
            hm += s_mx[c]  * w;
        }
        h_avg[t] = fmaxf(ha, 0.0f);
        h_mx[t]  = fmaxf(hm, 0.0f);
    }
    __syncthreads();
    float o = 0.0f;
    #pragma unroll
    for (int r = 0; r < CR; r++)
        o += (h_avg[r] + h_mx[r]) * fc2[t * CR + r];
    d_ca[b * CC + t] = 1.0f / (1.0f + expf(-o));
}

// ---------------- K3: per-(b,pixel) mean & max over channels of x*ca ----------------
__global__ void k_spatstats(const float* __restrict__ x) {
    const int b = blockIdx.x >> 4;                         // 16 blocks / batch
    const int n = ((blockIdx.x & 15) << 8) + threadIdx.x;  // pixel
    __shared__ float ca[CC];
    if (threadIdx.x < CC) ca[threadIdx.x] = d_ca[b * CC + threadIdx.x];
    __syncthreads();
    const float* xb = x + (size_t)b * CC * NPIX;
    float s = 0.0f, m = -INFINITY;
    #pragma unroll
    for (int c = 0; c < CC; c++) {
        const float v = xb[c * NPIX + n] * ca[c];
        s += v;
        m = fmaxf(m, v);
    }
    d_sa_avg[b * NPIX + n] = s * (1.0f / CC);
    d_sa_max[b * NPIX + n] = m;
}

// ---------------- K4: 7x7 conv (cross-correlation, pad 3) + sigmoid ----------------
__global__ void k_conv(const float* __restrict__ sw) {  // [1,2,7,7]
    const int b = blockIdx.x >> 4;
    const int n = ((blockIdx.x & 15) << 8) + threadIdx.x;
    const int h = n >> 6, w = n & 63;
    __shared__ float wgt[98];
    if (threadIdx.x < 98) wgt[threadIdx.x] = sw[threadIdx.x];
    __syncthreads();
    float acc = 0.0f;
    #pragma unroll
    for (int kh = 0; kh < 7; kh++) {
        const int ih = h + kh - 3;
        if (ih < 0 || ih >= HH) continue;
        #pragma unroll
        for (int kw = 0; kw < 7; kw++) {
            const int iw = w + kw - 3;
            if (iw < 0 || iw >= WWD) continue;
            const int idx = b * NPIX + ih * WWD + iw;
            acc += d_sa_avg[idx] * wgt[kh * 7 + kw]
                 + d_sa_max[idx] * wgt[49 + kh * 7 + kw];
        }
    }
    d_sa_mask[b * NPIX + n] = 1.0f / (1.0f + expf(-acc));
}

// ---------------- PAM fallback (executes only when gamma != 0) ----------------
__global__ void k_qk(const float* __restrict__ x,
                     const float* __restrict__ qw, const float* __restrict__ qb,
                     const float* __restrict__ kw, const float* __restrict__ kb,
                     const float* __restrict__ gamma) {
    if (gamma[0] == 0.0f) return;
    const int b = blockIdx.x >> 4;
    const int n = ((blockIdx.x & 15) << 8) + threadIdx.x;
    __shared__ float sqw[CR * CC], skw[CR * CC], sqb[CR], skb[CR];
    for (int i = threadIdx.x; i < CR * CC; i += blockDim.x) { sqw[i] = qw[i]; skw[i] = kw[i]; }
    if (threadIdx.x < CR) { sqb[threadIdx.x] = qb[threadIdx.x]; skb[threadIdx.x] = kb[threadIdx.x]; }
    __syncthreads();
    const float* xb = x + (size_t)b * CC * NPIX + n;
    float qa[CR], ka[CR];
    #pragma unroll
    for (int r = 0; r < CR; r++) { qa[r] = sqb[r]; ka[r] = skb[r]; }
    for (int c = 0; c < CC; c++) {
        const float xv = xb[c * NPIX];
        #pragma unroll
        for (int r = 0; r < CR; r++) {
            qa[r] += xv * sqw[r * CC + c];
            ka[r] += xv * skw[r * CC + c];
        }
    }
    #pragma unroll
    for (int r = 0; r < CR; r++) {
        d_q[(b * CR + r) * NPIX + n] = qa[r];
        d_k[(b * CR + r) * NPIX + n] = ka[r];
    }
}

__global__ void k_vproj(const float* __restrict__ x,
                        const float* __restrict__ vw, const float* __restrict__ vb,
                        const float* __restrict__ gamma) {
    if (gamma[0] == 0.0f) return;
    const int bcn = blockIdx.x * blockDim.x + threadIdx.x;  // over B*C*NPIX
    const int bc = bcn / NPIX;
    const int b = bc / CC, c = bc % CC, n = bcn % NPIX;
    const float* xb = x + (size_t)b * CC * NPIX + n;
    float acc = vb[c];
    for (int cc = 0; cc < CC; cc++) acc += xb[cc * NPIX] * vw[c * CC + cc];
    d_v[bcn] = acc;
}

__global__ void k_attn(const float* __restrict__ gamma) {
    if (gamma[0] == 0.0f) return;
    const int b = blockIdx.x / NPIX;
    const int i = blockIdx.x % NPIX;
    __shared__ float att[NPIX];
    __shared__ float red[256];
    float qr[CR];
    #pragma unroll
    for (int r = 0; r < CR; r++) qr[r] = d_q[(b * CR + r) * NPIX + i];
    float mx = -INFINITY;
    for (int j = threadIdx.x; j < NPIX; j += 256) {
        float e = 0.0f;
        #pragma unroll
        for (int r = 0; r < CR; r++) e += qr[r] * d_k[(b * CR + r) * NPIX + j];
        att[j] = e;
        mx = fmaxf(mx, e);
    }
    red[threadIdx.x] = mx; __syncthreads();
    for (int s = 128; s > 0; s >>= 1) {
        if (threadIdx.x < s) red[threadIdx.x] = fmaxf(red[threadIdx.x], red[threadIdx.x + s]);
        __syncthreads();
    }
    mx = red[0]; __syncthreads();
    float sum = 0.0f;
    for (int j = threadIdx.x; j < NPIX; j += 256) {
        const float e = expf(att[j] - mx);
        att[j] = e;
        sum += e;
    }
    red[threadIdx.x] = sum; __syncthreads();
    for (int s = 128; s > 0; s >>= 1) {
        if (threadIdx.x < s) red[threadIdx.x] += red[threadIdx.x + s];
        __syncthreads();
    }
    const float inv = 1.0f / red[0]; __syncthreads();
    for (int c = 0; c < CC; c++) {
        float acc = 0.0f;
        for (int j = threadIdx.x; j < NPIX; j += 256)
            acc += att[j] * d_v[(b * CC + c) * NPIX + j];
        red[threadIdx.x] = acc; __syncthreads();
        for (int s = 128; s > 0; s >>= 1) {
            if (threadIdx.x < s) red[threadIdx.x] += red[threadIdx.x + s];
            __syncthreads();
        }
        if (threadIdx.x == 0) d_pam[(b * CC + c) * NPIX + i] = red[0] * inv;
        __syncthreads();
    }
}

// ---------------- K5: final combine ----------------
// out = x * (1 + ca*sa) + gamma*pam
__global__ void k_final(const float* __restrict__ x,
                        const float* __restrict__ gamma,
                        float* __restrict__ out) {
    const int i4  = blockIdx.x * blockDim.x + threadIdx.x;  // float4 index
    const int idx = i4 * 4;
    const int bc  = idx >> 12;          // idx / NPIX
    const int b   = bc >> 6;
    const int n   = idx & (NPIX - 1);
    const float ca = d_ca[bc];
    const float4 xv = reinterpret_cast<const float4*>(x)[i4];
    const float4 sm = *reinterpret_cast<const float4*>(&d_sa_mask[b * NPIX + n]);
    float4 o;
    o.x = xv.x * (1.0f + ca * sm.x);
    o.y = xv.y * (1.0f + ca * sm.y);
    o.z = xv.z * (1.0f + ca * sm.z);
    o.w = xv.w * (1.0f + ca * sm.w);
    const float g = gamma[0];
    if (g != 0.0f) {
        const float4 p = reinterpret_cast<const float4*>(d_pam)[i4];
        o.x += g * p.x; o.y += g * p.y; o.z += g * p.z; o.w += g * p.w;
    }
    reinterpret_cast<float4*>(out)[i4] = o;
}

// ---------------- launch ----------------
extern "C" void kernel_launch(void* const* d_in, const int* in_sizes, int n_in,
                              void* d_out, int out_size) {
    const float* x     = (const float*)d_in[0];
    const float* fc1_w = (const float*)d_in[1];
    const float* fc2_w = (const float*)d_in[2];
    const float* q_w   = (const float*)d_in[3];
    const float* q_b   = (const float*)d_in[4];
    const float* k_w   = (const float*)d_in[5];
    const float* k_b   = (const float*)d_in[6];
    const float* v_w   = (const float*)d_in[7];
    const float* v_b   = (const float*)d_in[8];
    const float* gamma = (const float*)d_in[9];
    const float* sa_w  = (const float*)d_in[10];
    float* out = (float*)d_out;

    // channel attention
    k_chanstats<<<BB * CC, 256>>>(x);
    k_mlp<<<BB, CC>>>(fc1_w, fc2_w);
    // spatial attention
    k_spatstats<<<BB * 16, 256>>>(x);
    k_conv<<<BB * 16, 256>>>(sa_w);
    // PAM (early-exits when gamma == 0)
    k_qk<<<BB * 16, 256>>>(x, q_w, q_b, k_w, k_b, gamma);
    k_vproj<<<BB * CC * 16, 256>>>(x, v_w, v_b, gamma);
    k_attn<<<BB * NPIX, 256>>>(gamma);
    // combine
    k_final<<<(BB * CC * NPIX) / (256 * 4), 256>>>(x, gamma, out);
}

// round 2
// speedup vs baseline: 1.9863x; 1.9863x over previous
#include <cuda_runtime.h>
#include <math.h>

#define BB   8
#define CC   64
#define CR   8
#define HH   64
#define WWD  64
#define NPIX 4096   // HH*WWD

// ---------------- device scratch (static, no allocation) ----------------
__device__ float d_avg[BB * CC];
__device__ float d_maxv[BB * CC];
__device__ float d_ca[BB * CC];
__device__ float d_sa_avg[BB * NPIX];
__device__ float d_sa_max[BB * NPIX];
// PAM fallback scratch (only written when gamma != 0)
__device__ float d_q[BB * CR * NPIX];
__device__ float d_k[BB * CR * NPIX];
__device__ float d_v[BB * CC * NPIX];
__device__ float d_pam[BB * CC * NPIX];

// ---------------- K1: per-(b,c) mean & max over HW ----------------
__global__ void k_chanstats(const float* __restrict__ x) {
    const int bc = blockIdx.x;                 // 0 .. B*C-1
    const float4* xp = reinterpret_cast<const float4*>(x + (size_t)bc * NPIX);
    float s = 0.0f, m = -INFINITY;
    #pragma unroll 4
    for (int i = threadIdx.x; i < NPIX / 4; i += 256) {
        float4 v = xp[i];
        s += (v.x + v.y) + (v.z + v.w);
        m = fmaxf(m, fmaxf(fmaxf(v.x, v.y), fmaxf(v.z, v.w)));
    }
    for (int off = 16; off > 0; off >>= 1) {
        s += __shfl_down_sync(0xffffffffu, s, off);
        m  = fmaxf(m, __shfl_down_sync(0xffffffffu, m, off));
    }
    __shared__ float ss[8], sm[8];
    const int wid = threadIdx.x >> 5, lid = threadIdx.x & 31;
    if (lid == 0) { ss[wid] = s; sm[wid] = m; }
    __syncthreads();
    if (threadIdx.x == 0) {
        float ts = 0.0f, tm = -INFINITY;
        #pragma unroll
        for (int i = 0; i < 8; i++) { ts += ss[i]; tm = fmaxf(tm, sm[i]); }
        d_avg[bc]  = ts * (1.0f / NPIX);
        d_maxv[bc] = tm;
    }
}

// ---------------- K2: channel-attention MLP (one block per batch) ----------------
__global__ void k_mlp(const float* __restrict__ fc1,   // [CR, C]
                      const float* __restrict__ fc2) { // [C, CR]
    const int b = blockIdx.x;
    const int t = threadIdx.x;  // 64 threads
    __shared__ float s_avg[CC], s_mx[CC], h_avg[CR], h_mx[CR];
    s_avg[t] = d_avg[b * CC + t];
    s_mx[t]  = d_maxv[b * CC + t];
    __syncthreads();
    if (t < CR) {
        float ha = 0.0f, hm = 0.0f;
        #pragma unroll
        for (int c = 0; c < CC; c++) {
            const float w = fc1[t * CC + c];
            ha += s_avg[c] * w;
            hm += s_mx[c]  * w;
        }
        h_avg[t] = fmaxf(ha, 0.0f);
        h_mx[t]  = fmaxf(hm, 0.0f);
    }
    __syncthreads();
    float o = 0.0f;
    #pragma unroll
    for (int r = 0; r < CR; r++)
        o += (h_avg[r] + h_mx[r]) * fc2[t * CR + r];
    d_ca[b * CC + t] = 1.0f / (1.0f + expf(-o));
}

// ---------------- K3: per-(b,pixel) mean & max over channels of x*ca ----------------
__global__ void k_spatstats(const float* __restrict__ x) {
    const int b = blockIdx.x >> 4;                         // 16 blocks / batch
    const int n = ((blockIdx.x & 15) << 8) + threadIdx.x;  // pixel
    __shared__ float ca[CC];
    if (threadIdx.x < CC) ca[threadIdx.x] = d_ca[b * CC + threadIdx.x];
    __syncthreads();
    const float* xb = x + (size_t)b * CC * NPIX;
    float s = 0.0f, m = -INFINITY;
    #pragma unroll
    for (int c = 0; c < CC; c++) {
        const float v = xb[c * NPIX + n] * ca[c];
        s += v;
        m = fmaxf(m, v);
    }
    d_sa_avg[b * NPIX + n] = s * (1.0f / CC);
    d_sa_max[b * NPIX + n] = m;
}

// ---------------- K4: FUSED 7x7 conv + sigmoid + final combine ----------------
// grid: 512 blocks = b(8) x pixel-chunk(16, 256 px each) x channel-group(4, 16 ch each)
// out = x * (1 + ca*sa_mask) + gamma*pam
__global__ void k_conv_final(const float* __restrict__ x,
                             const float* __restrict__ sw,     // [2,7,7]
                             const float* __restrict__ gamma,
                             float* __restrict__ out) {
    const int blk   = blockIdx.x;
    const int b     = blk >> 6;          // 0..7
    const int chunk = (blk >> 2) & 15;   // 0..15 -> pixels chunk*256
    const int cg    = blk & 3;           // channel group (16 channels)
    const int t     = threadIdx.x;       // 256 threads
    const int n0    = chunk << 8;        // first pixel
    const int h0    = chunk << 2;        // first row (4 rows per chunk)

    __shared__ float s_avg[10][70];      // rows h0-3 .. h0+6, cols -3..66
    __shared__ float s_max[10][70];
    __shared__ float wgt[98];
    __shared__ float mask[256];
    __shared__ float s_ca[16];

    if (t < 98) wgt[t] = sw[t];
    if (t < 16) s_ca[t] = d_ca[b * CC + cg * 16 + t];

    // load halo tile (zero-padded), 700 elements
    for (int i = t; i < 700; i += 256) {
        const int r = i / 70, cidx = i % 70;
        const int gh = h0 - 3 + r, gw = cidx - 3;
        float a = 0.0f, mval = 0.0f;
        if (gh >= 0 && gh < HH && gw >= 0 && gw < WWD) {
            const int gi = b * NPIX + gh * WWD + gw;
            a    = d_sa_avg[gi];
            mval = d_sa_max[gi];
        }
        s_avg[r][cidx] = a;
        s_max[r][cidx] = mval;
    }
    __syncthreads();

    // conv for this block's 256 pixels
    {
        const int h = t >> 6;   // 0..3 local row
        const int w = t & 63;   // col
        float acc = 0.0f;
        #pragma unroll
        for (int kh = 0; kh < 7; kh++) {
            #pragma unroll
            for (int kw = 0; kw < 7; kw++) {
                acc += s_avg[h + kh][w + kw] * wgt[kh * 7 + kw]
                     + s_max[h + kh][w + kw] * wgt[49 + kh * 7 + kw];
            }
        }
        mask[t] = 1.0f / (1.0f + expf(-acc));
    }
    __syncthreads();

    const float g = gamma[0];
    const float* xb = x + (size_t)(b * CC + cg * 16) * NPIX + n0;
    float* ob = out + (size_t)(b * CC + cg * 16) * NPIX + n0;
    const float msk = mask[t];
    if (g == 0.0f) {
        #pragma unroll
        for (int c = 0; c < 16; c++) {
            const float scale = 1.0f + s_ca[c] * msk;
            ob[c * NPIX + t] = xb[c * NPIX + t] * scale;
        }
    } else {
        const float* pb = d_pam + (size_t)(b * CC + cg * 16) * NPIX + n0;
        #pragma unroll
        for (int c = 0; c < 16; c++) {
            const float scale = 1.0f + s_ca[c] * msk;
            ob[c * NPIX + t] = xb[c * NPIX + t] * scale + g * pb[c * NPIX + t];
        }
    }
}

// ---------------- PAM fallback (executes only when gamma != 0) ----------------
__global__ void k_pam_qkv(const float* __restrict__ x,
                          const float* __restrict__ qw, const float* __restrict__ qb,
                          const float* __restrict__ kw, const float* __restrict__ kb,
                          const float* __restrict__ vw, const float* __restrict__ vb,
                          const float* __restrict__ gamma) {
    if (gamma[0] == 0.0f) return;
    __shared__ float sqw[CR * CC], skw[CR * CC], sqb[CR], skb[CR];
    for (int i = threadIdx.x; i < CR * CC; i += blockDim.x) { sqw[i] = qw[i]; skw[i] = kw[i]; }
    if (threadIdx.x < CR) { sqb[threadIdx.x] = qb[threadIdx.x]; skb[threadIdx.x] = kb[threadIdx.x]; }
    __syncthreads();
    // q,k: grid-stride over B*NPIX
    for (int bn = blockIdx.x * blockDim.x + threadIdx.x; bn < BB * NPIX;
         bn += gridDim.x * blockDim.x) {
        const int b = bn >> 12, n = bn & (NPIX - 1);
        const float* xb = x + (size_t)b * CC * NPIX + n;
        float qa[CR], ka[CR];
        #pragma unroll
        for (int r = 0; r < CR; r++) { qa[r] = sqb[r]; ka[r] = skb[r]; }
        for (int c = 0; c < CC; c++) {
            const float xv = xb[c * NPIX];
            #pragma unroll
            for (int r = 0; r < CR; r++) {
                qa[r] += xv * sqw[r * CC + c];
                ka[r] += xv * skw[r * CC + c];
            }
        }
        #pragma unroll
        for (int r = 0; r < CR; r++) {
            d_q[(b * CR + r) * NPIX + n] = qa[r];
            d_k[(b * CR + r) * NPIX + n] = ka[r];
        }
    }
    // v: grid-stride over B*C*NPIX
    for (int bcn = blockIdx.x * blockDim.x + threadIdx.x; bcn < BB * CC * NPIX;
         bcn += gridDim.x * blockDim.x) {
        const int bc = bcn >> 12;
        const int b = bc >> 6, c = bc & 63, n = bcn & (NPIX - 1);
        const float* xb = x + (size_t)b * CC * NPIX + n;
        float acc = vb[c];
        for (int cc = 0; cc < CC; cc++) acc += xb[cc * NPIX] * vw[c * CC + cc];
        d_v[bcn] = acc;
    }
}

__global__ void k_pam_attn(const float* __restrict__ gamma) {
    if (gamma[0] == 0.0f) return;
    __shared__ float att[NPIX];
    __shared__ float red[256];
    for (int row = blockIdx.x; row < BB * NPIX; row += gridDim.x) {
        const int b = row >> 12;
        const int i = row & (NPIX - 1);
        float qr[CR];
        #pragma unroll
        for (int r = 0; r < CR; r++) qr[r] = d_q[(b * CR + r) * NPIX + i];
        float mx = -INFINITY;
        for (int j = threadIdx.x; j < NPIX; j += 256) {
            float e = 0.0f;
            #pragma unroll
            for (int r = 0; r < CR; r++) e += qr[r] * d_k[(b * CR + r) * NPIX + j];
            att[j] = e;
            mx = fmaxf(mx, e);
        }
        red[threadIdx.x] = mx; __syncthreads();
        for (int s = 128; s > 0; s >>= 1) {
            if (threadIdx.x < s) red[threadIdx.x] = fmaxf(red[threadIdx.x], red[threadIdx.x + s]);
            __syncthreads();
        }
        mx = red[0]; __syncthreads();
        float sum = 0.0f;
        for (int j = threadIdx.x; j < NPIX; j += 256) {
            const float e = expf(att[j] - mx);
            att[j] = e;
            sum += e;
        }
        red[threadIdx.x] = sum; __syncthreads();
        for (int s = 128; s > 0; s >>= 1) {
            if (threadIdx.x < s) red[threadIdx.x] += red[threadIdx.x + s];
            __syncthreads();
        }
        const float inv = 1.0f / red[0]; __syncthreads();
        for (int c = 0; c < CC; c++) {
            float acc = 0.0f;
            for (int j = threadIdx.x; j < NPIX; j += 256)
                acc += att[j] * d_v[(b * CC + c) * NPIX + j];
            red[threadIdx.x] = acc; __syncthreads();
            for (int s = 128; s > 0; s >>= 1) {
                if (threadIdx.x < s) red[threadIdx.x] += red[threadIdx.x + s];
                __syncthreads();
            }
            if (threadIdx.x == 0) d_pam[(b * CC + c) * NPIX + i] = red[0] * inv;
            __syncthreads();
        }
    }
}

// ---------------- launch ----------------
extern "C" void kernel_launch(void* const* d_in, const int* in_sizes, int n_in,
                              void* d_out, int out_size) {
    const float* x     = (const float*)d_in[0];
    const float* fc1_w = (const float*)d_in[1];
    const float* fc2_w = (const float*)d_in[2];
    const float* q_w   = (const float*)d_in[3];
    const float* q_b   = (const float*)d_in[4];
    const float* k_w   = (const float*)d_in[5];
    const float* k_b   = (const float*)d_in[6];
    const float* v_w   = (const float*)d_in[7];
    const float* v_b   = (const float*)d_in[8];
    const float* gamma = (const float*)d_in[9];
    const float* sa_w  = (const float*)d_in[10];
    float* out = (float*)d_out;

    // channel attention
    k_chanstats<<<BB * CC, 256>>>(x);
    k_mlp<<<BB, CC>>>(fc1_w, fc2_w);
    // spatial attention stats
    k_spatstats<<<BB * 16, 256>>>(x);
    // PAM fallback (cheap early-exit when gamma==0)
    k_pam_qkv<<<512, 256>>>(x, q_w, q_b, k_w, k_b, v_w, v_b, gamma);
    k_pam_attn<<<512, 256>>>(gamma);
    // fused conv + sigmoid + final combine
    k_conv_final<<<512, 256>>>(x, sa_w, gamma, out);
}